// round 1
// baseline (speedup 1.0000x reference)
#include <cuda_runtime.h>
#include <cstdint>

#define N_NODES 20000
#define N_EDGES 1280000
#define IN_DIM 16
#define HID 128
#define G3 384
#define OUT_DIM 4

// ---------------- scratch (static device globals; no allocation) ----------------
__device__ float g_deg[N_NODES];
__device__ float g_s[N_NODES * HID];      // (x@W_gcn) * dinv  (messages, pre-scaled)
__device__ float g_agg[N_NODES * HID];    // scatter-add accumulator (init = self term)
__device__ float g_xg[N_NODES * G3];      // precomputed input gates
__device__ float g_ys[N_NODES * HID];     // GRU outputs

// ---------------- packed f32x2 helpers ----------------
__device__ __forceinline__ unsigned long long ffma2(unsigned long long a,
                                                    unsigned long long b,
                                                    unsigned long long c) {
    unsigned long long d;
    asm("fma.rn.f32x2 %0, %1, %2, %3;" : "=l"(d) : "l"(a), "l"(b), "l"(c));
    return d;
}
__device__ __forceinline__ float2 u2f2(unsigned long long u) {
    float2 f;
    asm("mov.b64 {%0, %1}, %2;" : "=f"(f.x), "=f"(f.y) : "l"(u));
    return f;
}

// ---------------- K1: deg init (self-loop => 1) ----------------
__global__ void k_init_deg() {
    int i = blockIdx.x * blockDim.x + threadIdx.x;
    if (i < N_NODES) g_deg[i] = 1.0f;
}

// ---------------- K2: in-degree over targets ----------------
__global__ void k_deg(const int* __restrict__ ei) {
    int e = blockIdx.x * blockDim.x + threadIdx.x;
    if (e < N_EDGES) atomicAdd(&g_deg[ei[N_EDGES + e]], 1.0f);
}

// ---------------- K3: s = (x @ W_gcn) * dinv ; agg init with self term ----------------
__global__ void k_lin(const float* __restrict__ x, const float* __restrict__ Wg) {
    __shared__ float sx[IN_DIM];
    int node = blockIdx.x;
    int tid = threadIdx.x;  // 128 threads
    if (tid < IN_DIM) sx[tid] = x[node * IN_DIM + tid];
    __syncthreads();
    float acc = 0.0f;
#pragma unroll
    for (int k = 0; k < IN_DIM; k++) acc = fmaf(sx[k], Wg[k * HID + tid], acc);
    float s = acc * rsqrtf(g_deg[node]);
    g_s[(size_t)node * HID + tid] = s;
    g_agg[(size_t)node * HID + tid] = s;  // self-loop contribution (pre outer dinv)
}

// ---------------- K4: scatter-add messages ----------------
__global__ void k_scatter(const int* __restrict__ ei) {
    long long gid = (long long)blockIdx.x * blockDim.x + threadIdx.x;
    if (gid >= (long long)N_EDGES * HID) return;
    int e = (int)(gid >> 7);
    int d = (int)(gid & 127);
    int r = ei[e];
    int c = ei[N_EDGES + e];
    atomicAdd(&g_agg[(size_t)c * HID + d], g_s[(size_t)r * HID + d]);
}

// ---------------- K5: xg = (agg*dinv + b_gcn) @ W_ih.T + b_ih ----------------
// Persistent: each thread keeps its W_ih row (128 floats) in registers.
__global__ void __launch_bounds__(G3, 1)
k_xg(const float* __restrict__ Wih, const float* __restrict__ bih,
     const float* __restrict__ bgcn) {
    __shared__ __align__(16) float sg[HID];
    int tid = threadIdx.x;
    unsigned long long w[HID / 2];
    const unsigned long long* wr =
        (const unsigned long long*)(Wih + (size_t)tid * HID);
#pragma unroll
    for (int m = 0; m < HID / 2; m++) w[m] = wr[m];
    float b = bih[tid];
    float bg = (tid < HID) ? bgcn[tid] : 0.0f;

    for (int node = blockIdx.x; node < N_NODES; node += gridDim.x) {
        __syncthreads();  // protect sg from previous iteration's readers
        if (tid < HID) {
            float dv = rsqrtf(g_deg[node]);
            sg[tid] = fmaf(g_agg[(size_t)node * HID + tid], dv, bg);
        }
        __syncthreads();
        unsigned long long a0 = 0ull, a1 = 0ull;
        const ulonglong2* hp = (const ulonglong2*)sg;
#pragma unroll
        for (int m = 0; m < HID / 4; m++) {
            ulonglong2 hv = hp[m];
            a0 = ffma2(w[2 * m], hv.x, a0);
            a1 = ffma2(w[2 * m + 1], hv.y, a1);
        }
        float2 f0 = u2f2(a0), f1 = u2f2(a1);
        g_xg[(size_t)node * G3 + tid] = f0.x + f0.y + f1.x + f1.y + b;
    }
}

// ---------------- K6: sequential GRU scan (single CTA, persistent) ----------------
__global__ void __launch_bounds__(G3, 1)
k_gru(const float* __restrict__ Whh, const float* __restrict__ bhh,
      const float* __restrict__ h0, float* __restrict__ hT) {
    __shared__ __align__(16) float sh_h[HID];
    __shared__ float sh_hg[G3];
    __shared__ float sh_xg[G3];
    int tid = threadIdx.x;

    // W_hh row -> registers (64 packed pairs = 128 regs)
    unsigned long long w[HID / 2];
    const unsigned long long* wr =
        (const unsigned long long*)(Whh + (size_t)tid * HID);
#pragma unroll
    for (int m = 0; m < HID / 2; m++) w[m] = wr[m];
    float bh = bhh[tid];

    if (tid < HID) sh_h[tid] = h0[tid];
    float xg_cur = g_xg[tid];  // t = 0 prefetch
    __syncthreads();

    for (int t = 0; t < N_NODES; t++) {
        sh_xg[tid] = xg_cur;
        // hg[tid] = dot(W_hh[tid,:], h) + b_hh[tid]  — packed f32x2
        unsigned long long a0 = 0ull, a1 = 0ull;
        const ulonglong2* hp = (const ulonglong2*)sh_h;
#pragma unroll
        for (int m = 0; m < HID / 4; m++) {
            ulonglong2 hv = hp[m];
            a0 = ffma2(w[2 * m], hv.x, a0);
            a1 = ffma2(w[2 * m + 1], hv.y, a1);
        }
        float2 f0 = u2f2(a0), f1 = u2f2(a1);
        sh_hg[tid] = f0.x + f0.y + f1.x + f1.y + bh;
        if (t + 1 < N_NODES) xg_cur = g_xg[(size_t)(t + 1) * G3 + tid];
        __syncthreads();  // hg + xg staged

        if (tid < HID) {  // gate phase: warps 0-3, one per SMSP
            float xr = sh_xg[tid], xz = sh_xg[HID + tid], xn = sh_xg[2 * HID + tid];
            float hr = sh_hg[tid], hz = sh_hg[HID + tid], hn = sh_hg[2 * HID + tid];
            float r = 1.0f / (1.0f + __expf(-(xr + hr)));
            float z = 1.0f / (1.0f + __expf(-(xz + hz)));
            float narg = xn + r * hn;
            float n = 2.0f / (1.0f + __expf(-2.0f * narg)) - 1.0f;  // accurate tanh
            float h_old = sh_h[tid];
            float hnew = n + z * (h_old - n);  // (1-z)*n + z*h
            sh_h[tid] = hnew;
            g_ys[(size_t)t * HID + tid] = hnew;
        }
        __syncthreads();  // h updated before next dot / xg restage
    }
    if (tid < HID) hT[tid] = sh_h[tid];
}

// ---------------- K7: readout + output assembly ----------------
__global__ void k_readout(const float* __restrict__ x, const float* __restrict__ Wfc,
                          const float* __restrict__ bfc, float* __restrict__ out) {
    int warp = (blockIdx.x * blockDim.x + threadIdx.x) >> 5;
    int lane = threadIdx.x & 31;
    if (warp >= N_NODES) return;
    const float* y = g_ys + (size_t)warp * HID;
    float y0 = y[lane], y1 = y[lane + 32], y2 = y[lane + 64], y3 = y[lane + 96];
    float o[4];
#pragma unroll
    for (int c = 0; c < 4; c++) {
        float p = y0 * Wfc[lane * 4 + c];
        p = fmaf(y1, Wfc[(lane + 32) * 4 + c], p);
        p = fmaf(y2, Wfc[(lane + 64) * 4 + c], p);
        p = fmaf(y3, Wfc[(lane + 96) * 4 + c], p);
#pragma unroll
        for (int off = 16; off; off >>= 1) p += __shfl_xor_sync(0xffffffffu, p, off);
        o[c] = p;  // all lanes hold full sum after xor-reduce
    }
    float* nx = out + (size_t)warp * 8;
    if (lane < 3) nx[lane] = x[(size_t)warp * IN_DIM + lane];
    if (lane == 3) nx[7] = x[(size_t)warp * IN_DIM + 7];
    if (lane == 4) nx[3] = o[0] + bfc[0];
    if (lane == 5) nx[4] = o[1] + bfc[1];
    if (lane == 6) nx[5] = o[2] + bfc[2];
    if (lane == 7) nx[6] = o[3] + bfc[3];
}

// ---------------- launch ----------------
extern "C" void kernel_launch(void* const* d_in, const int* in_sizes, int n_in,
                              void* d_out, int out_size) {
    const float* x   = (const float*)d_in[0];
    const int*   ei  = (const int*)d_in[1];
    const float* h0  = (const float*)d_in[2];
    const float* Wg  = (const float*)d_in[3];
    const float* bg  = (const float*)d_in[4];
    const float* Wih = (const float*)d_in[5];
    const float* Whh = (const float*)d_in[6];
    const float* bih = (const float*)d_in[7];
    const float* bhh = (const float*)d_in[8];
    const float* Wfc = (const float*)d_in[9];
    const float* bfc = (const float*)d_in[10];
    float* out = (float*)d_out;

    k_init_deg<<<(N_NODES + 255) / 256, 256>>>();
    k_deg<<<(N_EDGES + 255) / 256, 256>>>(ei);
    k_lin<<<N_NODES, HID>>>(x, Wg);
    long long scat_threads = (long long)N_EDGES * HID;
    k_scatter<<<(int)((scat_threads + 255) / 256), 256>>>(ei);
    k_xg<<<148, G3>>>(Wih, bih, bg);
    k_gru<<<1, G3>>>(Whh, bhh, h0, out + (size_t)N_NODES * 8);
    k_readout<<<(N_NODES + 7) / 8, 256>>>(x, Wfc, bfc, out);
}

// round 2
// speedup vs baseline: 1.1154x; 1.1154x over previous
#include <cuda_runtime.h>
#include <cstdint>

#define N_NODES 20000
#define N_EDGES 1280000
#define IN_DIM 16
#define HID 128
#define G3 384
#define OUT_DIM 4

// ---------------- scratch (static device globals; no allocation) ----------------
__device__ float g_deg[N_NODES];
__device__ float g_s[N_NODES * HID];      // (x@W_gcn) * dinv  (messages, pre-scaled)
__device__ float g_agg[N_NODES * HID];    // scatter-add accumulator (init = self term)
__device__ float g_xg[N_NODES * G3];      // precomputed input gates
__device__ float g_ys[N_NODES * HID];     // GRU outputs

// ---------------- packed f32x2 helpers ----------------
__device__ __forceinline__ unsigned long long ffma2(unsigned long long a,
                                                    unsigned long long b,
                                                    unsigned long long c) {
    unsigned long long d;
    asm("fma.rn.f32x2 %0, %1, %2, %3;" : "=l"(d) : "l"(a), "l"(b), "l"(c));
    return d;
}
__device__ __forceinline__ float2 u2f2(unsigned long long u) {
    float2 f;
    asm("mov.b64 {%0, %1}, %2;" : "=f"(f.x), "=f"(f.y) : "l"(u));
    return f;
}

// ---------------- K1: deg init (self-loop => 1) ----------------
__global__ void k_init_deg() {
    int i = blockIdx.x * blockDim.x + threadIdx.x;
    if (i < N_NODES) g_deg[i] = 1.0f;
}

// ---------------- K2: in-degree over targets ----------------
__global__ void k_deg(const int* __restrict__ ei) {
    int e = blockIdx.x * blockDim.x + threadIdx.x;
    if (e < N_EDGES) atomicAdd(&g_deg[ei[N_EDGES + e]], 1.0f);
}

// ---------------- K3: s = (x @ W_gcn) * dinv ; agg init with self term ----------------
__global__ void k_lin(const float* __restrict__ x, const float* __restrict__ Wg) {
    __shared__ float sx[IN_DIM];
    int node = blockIdx.x;
    int tid = threadIdx.x;  // 128 threads
    if (tid < IN_DIM) sx[tid] = x[node * IN_DIM + tid];
    __syncthreads();
    float acc = 0.0f;
#pragma unroll
    for (int k = 0; k < IN_DIM; k++) acc = fmaf(sx[k], Wg[k * HID + tid], acc);
    float s = acc * rsqrtf(g_deg[node]);
    g_s[(size_t)node * HID + tid] = s;
    g_agg[(size_t)node * HID + tid] = s;  // self-loop contribution (pre outer dinv)
}

// ---------------- K4: scatter-add messages (vector red.v2) ----------------
__global__ void k_scatter(const int* __restrict__ ei) {
    long long gid = (long long)blockIdx.x * blockDim.x + threadIdx.x;
    if (gid >= (long long)N_EDGES * (HID / 2)) return;
    int e = (int)(gid >> 6);          // 64 float2 chunks... (HID/2 = 64 per edge)
    int q = (int)(gid & 63);
    int r = ei[e];
    int c = ei[N_EDGES + e];
    const float2* src = (const float2*)(g_s + (size_t)r * HID) + q;
    float2 v = *src;
    float* dst = g_agg + (size_t)c * HID + 2 * q;
    asm volatile("red.global.v2.f32.add [%0], {%1, %2};"
                 :: "l"(dst), "f"(v.x), "f"(v.y) : "memory");
}

// ---------------- K5: xg = (agg*dinv + b_gcn) @ W_ih.T + b_ih ----------------
__global__ void __launch_bounds__(G3, 1)
k_xg(const float* __restrict__ Wih, const float* __restrict__ bih,
     const float* __restrict__ bgcn) {
    __shared__ __align__(16) float sg[HID];
    int tid = threadIdx.x;
    unsigned long long w[HID / 2];
    const unsigned long long* wr =
        (const unsigned long long*)(Wih + (size_t)tid * HID);
#pragma unroll
    for (int m = 0; m < HID / 2; m++) w[m] = wr[m];
    float b = bih[tid];
    float bg = (tid < HID) ? bgcn[tid] : 0.0f;

    for (int node = blockIdx.x; node < N_NODES; node += gridDim.x) {
        __syncthreads();
        if (tid < HID) {
            float dv = rsqrtf(g_deg[node]);
            sg[tid] = fmaf(g_agg[(size_t)node * HID + tid], dv, bg);
        }
        __syncthreads();
        unsigned long long a0 = 0ull, a1 = 0ull;
        const ulonglong2* hp = (const ulonglong2*)sg;
#pragma unroll
        for (int m = 0; m < HID / 4; m++) {
            ulonglong2 hv = hp[m];
            a0 = ffma2(w[2 * m], hv.x, a0);
            a1 = ffma2(w[2 * m + 1], hv.y, a1);
        }
        float2 f0 = u2f2(a0), f1 = u2f2(a1);
        g_xg[(size_t)node * G3 + tid] = f0.x + f0.y + f1.x + f1.y + b;
    }
}

// ---------------- K6: sequential GRU scan (single CTA, persistent) ----------------
// Thread tid owns row tid of W_hh. Groups: g0=r rows (tid<128), g1=z rows,
// g2=n rows. g0/g1 compute sigmoids pre-barrier (they hold hr/hz in regs),
// publish r,z via smem; g2 holds hn,xn in regs, finishes after bar.sync.
__global__ void __launch_bounds__(G3, 1)
k_gru(const float* __restrict__ Whh, const float* __restrict__ bhh,
      const float* __restrict__ h0, float* __restrict__ hT) {
    __shared__ __align__(16) float sh_h[HID];
    __shared__ float sh_r[HID];
    __shared__ float sh_z[HID];
    int tid = threadIdx.x;
    int grp = tid >> 7;       // 0,1,2
    int j = tid & 127;

    unsigned long long w[HID / 2];
    const unsigned long long* wr =
        (const unsigned long long*)(Whh + (size_t)tid * HID);
#pragma unroll
    for (int m = 0; m < HID / 2; m++) w[m] = wr[m];
    float bh = bhh[tid];

    if (tid < HID) sh_h[tid] = h0[tid];
    float xg_cur = g_xg[tid];  // t = 0 prefetch
    __syncthreads();

    for (int t = 0; t < N_NODES; t++) {
        // ---- dot: hg[tid] = W_hh[tid,:] . h + b_hh[tid] ----
        unsigned long long a0 = 0ull, a1 = 0ull, a2 = 0ull, a3 = 0ull;
        const ulonglong2* hp = (const ulonglong2*)sh_h;
#pragma unroll
        for (int m = 0; m < HID / 8; m++) {
            ulonglong2 u = hp[2 * m];
            ulonglong2 v = hp[2 * m + 1];
            a0 = ffma2(w[4 * m], u.x, a0);
            a1 = ffma2(w[4 * m + 1], u.y, a1);
            a2 = ffma2(w[4 * m + 2], v.x, a2);
            a3 = ffma2(w[4 * m + 3], v.y, a3);
        }
        float2 f0 = u2f2(a0), f1 = u2f2(a1), f2 = u2f2(a2), f3 = u2f2(a3);
        float hg = ((f0.x + f0.y) + (f1.x + f1.y)) +
                   ((f2.x + f2.y) + (f3.x + f3.y)) + bh;

        float xg_own = xg_cur;
        if (t + 1 < N_NODES) xg_cur = g_xg[(size_t)(t + 1) * G3 + tid];

        if (grp == 0) {
            sh_r[j] = 1.0f / (1.0f + __expf(-(xg_own + hg)));
            asm volatile("bar.arrive 1, %0;" :: "n"(G3));
        } else if (grp == 1) {
            sh_z[j] = 1.0f / (1.0f + __expf(-(xg_own + hg)));
            asm volatile("bar.arrive 1, %0;" :: "n"(G3));
        } else {
            float h_old = sh_h[j];  // stable since last full barrier
            asm volatile("bar.sync 1, %0;" :: "n"(G3));
            float r = sh_r[j];
            float z = sh_z[j];
            float narg = fmaf(r, hg, xg_own);          // xn + r*hn
            float e = __expf(-2.0f * narg);
            float n = 2.0f / (1.0f + e) - 1.0f;        // tanh
            float hnew = n + z * (h_old - n);          // (1-z)n + z h
            sh_h[j] = hnew;
            g_ys[(size_t)t * HID + j] = hnew;
        }
        __syncthreads();  // h updated & visible before next dot
    }
    if (tid < HID) hT[tid] = sh_h[tid];
}

// ---------------- K7: readout + output assembly ----------------
__global__ void k_readout(const float* __restrict__ x, const float* __restrict__ Wfc,
                          const float* __restrict__ bfc, float* __restrict__ out) {
    int warp = (blockIdx.x * blockDim.x + threadIdx.x) >> 5;
    int lane = threadIdx.x & 31;
    if (warp >= N_NODES) return;
    const float* y = g_ys + (size_t)warp * HID;
    float y0 = y[lane], y1 = y[lane + 32], y2 = y[lane + 64], y3 = y[lane + 96];
    float o[4];
#pragma unroll
    for (int c = 0; c < 4; c++) {
        float p = y0 * Wfc[lane * 4 + c];
        p = fmaf(y1, Wfc[(lane + 32) * 4 + c], p);
        p = fmaf(y2, Wfc[(lane + 64) * 4 + c], p);
        p = fmaf(y3, Wfc[(lane + 96) * 4 + c], p);
#pragma unroll
        for (int off = 16; off; off >>= 1) p += __shfl_xor_sync(0xffffffffu, p, off);
        o[c] = p;
    }
    float* nx = out + (size_t)warp * 8;
    if (lane < 3) nx[lane] = x[(size_t)warp * IN_DIM + lane];
    if (lane == 3) nx[7] = x[(size_t)warp * IN_DIM + 7];
    if (lane == 4) nx[3] = o[0] + bfc[0];
    if (lane == 5) nx[4] = o[1] + bfc[1];
    if (lane == 6) nx[5] = o[2] + bfc[2];
    if (lane == 7) nx[6] = o[3] + bfc[3];
}

// ---------------- launch ----------------
extern "C" void kernel_launch(void* const* d_in, const int* in_sizes, int n_in,
                              void* d_out, int out_size) {
    const float* x   = (const float*)d_in[0];
    const int*   ei  = (const int*)d_in[1];
    const float* h0  = (const float*)d_in[2];
    const float* Wg  = (const float*)d_in[3];
    const float* bg  = (const float*)d_in[4];
    const float* Wih = (const float*)d_in[5];
    const float* Whh = (const float*)d_in[6];
    const float* bih = (const float*)d_in[7];
    const float* bhh = (const float*)d_in[8];
    const float* Wfc = (const float*)d_in[9];
    const float* bfc = (const float*)d_in[10];
    float* out = (float*)d_out;

    k_init_deg<<<(N_NODES + 255) / 256, 256>>>();
    k_deg<<<(N_EDGES + 255) / 256, 256>>>(ei);
    k_lin<<<N_NODES, HID>>>(x, Wg);
    long long scat_threads = (long long)N_EDGES * (HID / 2);
    k_scatter<<<(int)((scat_threads + 255) / 256), 256>>>(ei);
    k_xg<<<148, G3>>>(Wih, bih, bg);
    k_gru<<<1, G3>>>(Whh, bhh, h0, out + (size_t)N_NODES * 8);
    k_readout<<<(N_NODES + 7) / 8, 256>>>(x, Wfc, bfc, out);
}